// round 1
// baseline (speedup 1.0000x reference)
#include <cuda_runtime.h>

#define BB 2
#define CC 64
#define FF 257
#define TT 500
#define DC 16
#define BN_EPS 1e-5f
#define SCALE 0.25f
#define NPIX (BB*FF*TT)

// Scratch (device globals; no allocation allowed)
__device__ float g_qf[BB*TT*FF*DC];   // [b][t][f][c]
__device__ float g_kf[BB*TT*FF*DC];   // [b][t][f][c]
__device__ float g_vv[BB*TT*FF*DC];   // [b][t][f][c]
__device__ float g_qt[BB*FF*TT*DC];   // [b][f][t][c]
__device__ float g_kt[BB*FF*TT*DC];   // [b][f][t][c]
__device__ float g_fo[BB*FF*TT*DC];   // [b][f][t][c]  (f_out, V of time-attn)

// ---------------------------------------------------------------------------
// Kernel 1: fused 1x1 convs (fqkv: 64->48, tqk: 64->32) + BN + PReLU,
// scatter into attention-friendly layouts.
// ---------------------------------------------------------------------------
__global__ __launch_bounds__(256) void asa_conv(
    const float* __restrict__ inp,
    const float* __restrict__ fw, const float* __restrict__ fb,
    const float* __restrict__ fg, const float* __restrict__ fbe,
    const float* __restrict__ fm, const float* __restrict__ fv,
    const float* __restrict__ fa,
    const float* __restrict__ tw, const float* __restrict__ tb,
    const float* __restrict__ tg, const float* __restrict__ tbe,
    const float* __restrict__ tm, const float* __restrict__ tv,
    const float* __restrict__ ta)
{
    __shared__ float ws[64][80];   // transposed [c][o], BN scale folded in
    __shared__ float sh[80];       // folded shift
    __shared__ float al[2];
    int tid = threadIdx.x;

    for (int idx = tid; idx < 80*64; idx += 256) {
        int o = idx / 64, c = idx % 64;
        float w, g, vv;
        if (o < 48) { w = fw[o*64+c]; g = fg[o]; vv = fv[o]; }
        else        { int o2 = o-48; w = tw[o2*64+c]; g = tg[o2]; vv = tv[o2]; }
        ws[c][o] = w * (g * rsqrtf(vv + BN_EPS));
    }
    if (tid < 80) {
        int o = tid;
        float g, vv, m, b, be;
        if (o < 48) { g=fg[o]; vv=fv[o]; m=fm[o]; b=fb[o]; be=fbe[o]; }
        else        { int o2=o-48; g=tg[o2]; vv=tv[o2]; m=tm[o2]; b=tb[o2]; be=tbe[o2]; }
        sh[o] = (b - m) * (g * rsqrtf(vv + BN_EPS)) + be;
    }
    if (tid == 0) { al[0] = fa[0]; al[1] = ta[0]; }
    __syncthreads();

    int p = blockIdx.x * 256 + tid;
    if (p >= NPIX) return;
    int t = p % TT;
    int f = (p / TT) % FF;
    int b = p / (TT*FF);

    float acc[80];
#pragma unroll
    for (int o = 0; o < 80; o++) acc[o] = 0.f;

    const float* xp = inp + (b*CC*FF + f)*TT + t;
#pragma unroll 4
    for (int c = 0; c < 64; c++) {
        float x = __ldg(xp + c*FF*TT);
        const float4* wr = (const float4*)ws[c];
#pragma unroll
        for (int o4 = 0; o4 < 20; o4++) {
            float4 w4 = wr[o4];
            acc[o4*4+0] = fmaf(x, w4.x, acc[o4*4+0]);
            acc[o4*4+1] = fmaf(x, w4.y, acc[o4*4+1]);
            acc[o4*4+2] = fmaf(x, w4.z, acc[o4*4+2]);
            acc[o4*4+3] = fmaf(x, w4.w, acc[o4*4+3]);
        }
    }

    float a0 = al[0], a1 = al[1];
    // fqkv: channel o -> (c = o/3, which = o%3)
    float yq[16], yk[16], yv[16];
#pragma unroll
    for (int c = 0; c < 16; c++) {
        float q = acc[3*c+0] + sh[3*c+0]; yq[c] = q >= 0.f ? q : a0*q;
        float k = acc[3*c+1] + sh[3*c+1]; yk[c] = k >= 0.f ? k : a0*k;
        float v = acc[3*c+2] + sh[3*c+2]; yv[c] = v >= 0.f ? v : a0*v;
    }
    int fbase = ((b*TT + t)*FF + f)*DC;
#pragma unroll
    for (int i = 0; i < 4; i++) {
        ((float4*)&g_qf[fbase])[i] = make_float4(yq[4*i],yq[4*i+1],yq[4*i+2],yq[4*i+3]);
        ((float4*)&g_kf[fbase])[i] = make_float4(yk[4*i],yk[4*i+1],yk[4*i+2],yk[4*i+3]);
        ((float4*)&g_vv[fbase])[i] = make_float4(yv[4*i],yv[4*i+1],yv[4*i+2],yv[4*i+3]);
    }
    // tqk: channel o2 -> (c = o2/2, which = o2%2)
    float zq[16], zk[16];
#pragma unroll
    for (int c = 0; c < 16; c++) {
        float q = acc[48+2*c+0] + sh[48+2*c+0]; zq[c] = q >= 0.f ? q : a1*q;
        float k = acc[48+2*c+1] + sh[48+2*c+1]; zk[c] = k >= 0.f ? k : a1*k;
    }
    int tbase = ((b*FF + f)*TT + t)*DC;
#pragma unroll
    for (int i = 0; i < 4; i++) {
        ((float4*)&g_qt[tbase])[i] = make_float4(zq[4*i],zq[4*i+1],zq[4*i+2],zq[4*i+3]);
        ((float4*)&g_kt[tbase])[i] = make_float4(zk[4*i],zk[4*i+1],zk[4*i+2],zk[4*i+3]);
    }
}

// ---------------------------------------------------------------------------
// Kernel 2: frequency attention. One CTA per (b,t). K,V in SMEM, online
// softmax per query row f (one thread per f).
// ---------------------------------------------------------------------------
__global__ __launch_bounds__(288) void asa_fattn()
{
    __shared__ float Ks[FF*DC];
    __shared__ float Vs[FF*DC];
    int bt = blockIdx.x;
    int b = bt / TT, t = bt % TT;
    int base = (b*TT + t)*FF*DC;
    int tid = threadIdx.x;
    for (int i = tid; i < FF*DC; i += 288) {
        Ks[i] = g_kf[base + i];
        Vs[i] = g_vv[base + i];
    }
    __syncthreads();
    if (tid >= FF) return;
    int f = tid;

    float q[16];
    const float4* qp = (const float4*)&g_qf[base + f*DC];
#pragma unroll
    for (int i = 0; i < 4; i++) {
        float4 q4 = qp[i];
        q[4*i+0] = q4.x * SCALE; q[4*i+1] = q4.y * SCALE;
        q[4*i+2] = q4.z * SCALE; q[4*i+3] = q4.w * SCALE;
    }
    float m = -3.0e38f, l = 0.f;
    float acc[16];
#pragma unroll
    for (int c = 0; c < 16; c++) acc[c] = 0.f;

    for (int y = 0; y < FF; y++) {
        const float4* kr = (const float4*)&Ks[y*DC];
        float s = 0.f;
#pragma unroll
        for (int i = 0; i < 4; i++) {
            float4 k4 = kr[i];
            s = fmaf(q[4*i+0], k4.x, s);
            s = fmaf(q[4*i+1], k4.y, s);
            s = fmaf(q[4*i+2], k4.z, s);
            s = fmaf(q[4*i+3], k4.w, s);
        }
        if (s > m) {
            float corr = __expf(m - s);
            l *= corr;
#pragma unroll
            for (int c = 0; c < 16; c++) acc[c] *= corr;
            m = s;
        }
        float pr = __expf(s - m);
        l += pr;
        const float4* vr = (const float4*)&Vs[y*DC];
#pragma unroll
        for (int i = 0; i < 4; i++) {
            float4 v4 = vr[i];
            acc[4*i+0] = fmaf(pr, v4.x, acc[4*i+0]);
            acc[4*i+1] = fmaf(pr, v4.y, acc[4*i+1]);
            acc[4*i+2] = fmaf(pr, v4.z, acc[4*i+2]);
            acc[4*i+3] = fmaf(pr, v4.w, acc[4*i+3]);
        }
    }
    float inv = 1.f / l;
    int obase = ((b*FF + f)*TT + t)*DC;
#pragma unroll
    for (int i = 0; i < 4; i++)
        ((float4*)&g_fo[obase])[i] =
            make_float4(acc[4*i]*inv, acc[4*i+1]*inv, acc[4*i+2]*inv, acc[4*i+3]*inv);
}

// ---------------------------------------------------------------------------
// Kernel 3: causal time attention + proj block + residual.
// One CTA per (b,f). Thread tid handles queries t=tid and t=499-tid.
// ---------------------------------------------------------------------------
__device__ __forceinline__ void proj_store(
    const float* __restrict__ pws, const float* __restrict__ psh, float alpha,
    const float* __restrict__ inp, float* __restrict__ out,
    int b, int f, int t, const float acc[16], float l)
{
    float o[16];
    float inv = 1.f / l;
#pragma unroll
    for (int c = 0; c < 16; c++) o[c] = acc[c] * inv;
    int base = b*CC*FF*TT + f*TT + t;
#pragma unroll 4
    for (int co = 0; co < 64; co++) {
        const float4* wr = (const float4*)&pws[co*16];
        float r = psh[co];
#pragma unroll
        for (int i = 0; i < 4; i++) {
            float4 w4 = wr[i];
            r = fmaf(w4.x, o[4*i+0], r);
            r = fmaf(w4.y, o[4*i+1], r);
            r = fmaf(w4.z, o[4*i+2], r);
            r = fmaf(w4.w, o[4*i+3], r);
        }
        r = r >= 0.f ? r : alpha * r;
        int idx = base + co*FF*TT;
        out[idx] = r + __ldg(&inp[idx]);
    }
}

extern __shared__ float sm3[];
__global__ __launch_bounds__(256) void asa_tattn(
    const float* __restrict__ inp,
    const float* __restrict__ pw, const float* __restrict__ pb,
    const float* __restrict__ pg, const float* __restrict__ pbe,
    const float* __restrict__ pm, const float* __restrict__ pv,
    const float* __restrict__ pa,
    float* __restrict__ out)
{
    float* Ks  = sm3;               // TT*DC
    float* Vs  = sm3 + TT*DC;       // TT*DC
    float* pws = Vs + TT*DC;        // 64*16
    float* psh = pws + 64*16;       // 64
    __shared__ float s_alpha;

    int bf = blockIdx.x;
    int b = bf / FF, f = bf % FF;
    int base = bf * TT * DC;
    int tid = threadIdx.x;

    for (int i = tid; i < TT*DC; i += 256) {
        Ks[i] = g_kt[base + i];
        Vs[i] = g_fo[base + i];
    }
    for (int i = tid; i < 64*16; i += 256) {
        int o = i >> 4;
        pws[i] = pw[i] * (pg[o] * rsqrtf(pv[o] + BN_EPS));
    }
    if (tid < 64) {
        int o = tid;
        psh[o] = (pb[o] - pm[o]) * (pg[o] * rsqrtf(pv[o] + BN_EPS)) + pbe[o];
    }
    if (tid == 0) s_alpha = pa[0];
    __syncthreads();

    if (tid >= 250) return;
    float alpha = s_alpha;
    int t1 = tid;          // short query
    int t2 = TT - 1 - tid; // long query; t2 >= t1 always

    float q1[16], q2[16];
    const float4* q1p = (const float4*)&g_qt[base + t1*DC];
    const float4* q2p = (const float4*)&g_qt[base + t2*DC];
#pragma unroll
    for (int i = 0; i < 4; i++) {
        float4 a = q1p[i], c = q2p[i];
        q1[4*i+0]=a.x*SCALE; q1[4*i+1]=a.y*SCALE; q1[4*i+2]=a.z*SCALE; q1[4*i+3]=a.w*SCALE;
        q2[4*i+0]=c.x*SCALE; q2[4*i+1]=c.y*SCALE; q2[4*i+2]=c.z*SCALE; q2[4*i+3]=c.w*SCALE;
    }
    float m1 = -3.0e38f, l1 = 0.f, m2 = -3.0e38f, l2 = 0.f;
    float a1[16], a2[16];
#pragma unroll
    for (int c = 0; c < 16; c++) { a1[c] = 0.f; a2[c] = 0.f; }

    for (int y = 0; y <= t2; y++) {
        const float4* kr = (const float4*)&Ks[y*DC];
        const float4* vr = (const float4*)&Vs[y*DC];
        float4 k0 = kr[0], k1 = kr[1], k2 = kr[2], k3 = kr[3];
        float4 v0 = vr[0], v1 = vr[1], v2 = vr[2], v3 = vr[3];

        // long query: always in range
        {
            float s = 0.f;
            s = fmaf(q2[0],k0.x,s);  s = fmaf(q2[1],k0.y,s);  s = fmaf(q2[2],k0.z,s);  s = fmaf(q2[3],k0.w,s);
            s = fmaf(q2[4],k1.x,s);  s = fmaf(q2[5],k1.y,s);  s = fmaf(q2[6],k1.z,s);  s = fmaf(q2[7],k1.w,s);
            s = fmaf(q2[8],k2.x,s);  s = fmaf(q2[9],k2.y,s);  s = fmaf(q2[10],k2.z,s); s = fmaf(q2[11],k2.w,s);
            s = fmaf(q2[12],k3.x,s); s = fmaf(q2[13],k3.y,s); s = fmaf(q2[14],k3.z,s); s = fmaf(q2[15],k3.w,s);
            if (s > m2) {
                float corr = __expf(m2 - s);
                l2 *= corr;
#pragma unroll
                for (int c = 0; c < 16; c++) a2[c] *= corr;
                m2 = s;
            }
            float pr = __expf(s - m2);
            l2 += pr;
            a2[0]  = fmaf(pr,v0.x,a2[0]);  a2[1]  = fmaf(pr,v0.y,a2[1]);
            a2[2]  = fmaf(pr,v0.z,a2[2]);  a2[3]  = fmaf(pr,v0.w,a2[3]);
            a2[4]  = fmaf(pr,v1.x,a2[4]);  a2[5]  = fmaf(pr,v1.y,a2[5]);
            a2[6]  = fmaf(pr,v1.z,a2[6]);  a2[7]  = fmaf(pr,v1.w,a2[7]);
            a2[8]  = fmaf(pr,v2.x,a2[8]);  a2[9]  = fmaf(pr,v2.y,a2[9]);
            a2[10] = fmaf(pr,v2.z,a2[10]); a2[11] = fmaf(pr,v2.w,a2[11]);
            a2[12] = fmaf(pr,v3.x,a2[12]); a2[13] = fmaf(pr,v3.y,a2[13]);
            a2[14] = fmaf(pr,v3.z,a2[14]); a2[15] = fmaf(pr,v3.w,a2[15]);
        }
        // short query: causal bound
        if (y <= t1) {
            float s = 0.f;
            s = fmaf(q1[0],k0.x,s);  s = fmaf(q1[1],k0.y,s);  s = fmaf(q1[2],k0.z,s);  s = fmaf(q1[3],k0.w,s);
            s = fmaf(q1[4],k1.x,s);  s = fmaf(q1[5],k1.y,s);  s = fmaf(q1[6],k1.z,s);  s = fmaf(q1[7],k1.w,s);
            s = fmaf(q1[8],k2.x,s);  s = fmaf(q1[9],k2.y,s);  s = fmaf(q1[10],k2.z,s); s = fmaf(q1[11],k2.w,s);
            s = fmaf(q1[12],k3.x,s); s = fmaf(q1[13],k3.y,s); s = fmaf(q1[14],k3.z,s); s = fmaf(q1[15],k3.w,s);
            if (s > m1) {
                float corr = __expf(m1 - s);
                l1 *= corr;
#pragma unroll
                for (int c = 0; c < 16; c++) a1[c] *= corr;
                m1 = s;
            }
            float pr = __expf(s - m1);
            l1 += pr;
            a1[0]  = fmaf(pr,v0.x,a1[0]);  a1[1]  = fmaf(pr,v0.y,a1[1]);
            a1[2]  = fmaf(pr,v0.z,a1[2]);  a1[3]  = fmaf(pr,v0.w,a1[3]);
            a1[4]  = fmaf(pr,v1.x,a1[4]);  a1[5]  = fmaf(pr,v1.y,a1[5]);
            a1[6]  = fmaf(pr,v1.z,a1[6]);  a1[7]  = fmaf(pr,v1.w,a1[7]);
            a1[8]  = fmaf(pr,v2.x,a1[8]);  a1[9]  = fmaf(pr,v2.y,a1[9]);
            a1[10] = fmaf(pr,v2.z,a1[10]); a1[11] = fmaf(pr,v2.w,a1[11]);
            a1[12] = fmaf(pr,v3.x,a1[12]); a1[13] = fmaf(pr,v3.y,a1[13]);
            a1[14] = fmaf(pr,v3.z,a1[14]); a1[15] = fmaf(pr,v3.w,a1[15]);
        }
    }
    proj_store(pws, psh, alpha, inp, out, b, f, t1, a1, l1);
    proj_store(pws, psh, alpha, inp, out, b, f, t2, a2, l2);
}

// ---------------------------------------------------------------------------
extern "C" void kernel_launch(void* const* d_in, const int* in_sizes, int n_in,
                              void* d_out, int out_size)
{
    const float* inp = (const float*)d_in[0];
    asa_conv<<<(NPIX + 255)/256, 256>>>(
        inp,
        (const float*)d_in[1],  (const float*)d_in[2],  (const float*)d_in[3],
        (const float*)d_in[4],  (const float*)d_in[5],  (const float*)d_in[6],
        (const float*)d_in[7],
        (const float*)d_in[8],  (const float*)d_in[9],  (const float*)d_in[10],
        (const float*)d_in[11], (const float*)d_in[12], (const float*)d_in[13],
        (const float*)d_in[14]);

    asa_fattn<<<BB*TT, 288>>>();

    int smem = (TT*DC*2 + 64*16 + 64) * (int)sizeof(float);
    cudaFuncSetAttribute(asa_tattn, cudaFuncAttributeMaxDynamicSharedMemorySize, smem);
    asa_tattn<<<BB*FF, 256, smem>>>(
        inp,
        (const float*)d_in[15], (const float*)d_in[16], (const float*)d_in[17],
        (const float*)d_in[18], (const float*)d_in[19], (const float*)d_in[20],
        (const float*)d_in[21],
        (float*)d_out);
}

// round 2
// speedup vs baseline: 1.0199x; 1.0199x over previous
#include <cuda_runtime.h>

#define BB 2
#define CC 64
#define FF 257
#define TT 500
#define TTP 512          // padded time rows in smem (chunk overread)
#define DC 16
#define BN_EPS 1e-5f
#define SCALE 0.25f
#define NPIX (BB*FF*TT)

typedef unsigned long long u64;

__device__ __forceinline__ u64 pk2(float lo, float hi) {
    u64 r; asm("mov.b64 %0, {%1,%2};" : "=l"(r) : "f"(lo), "f"(hi)); return r;
}
__device__ __forceinline__ void upk2(u64 v, float& lo, float& hi) {
    asm("mov.b64 {%0,%1}, %2;" : "=f"(lo), "=f"(hi) : "l"(v));
}
__device__ __forceinline__ u64 fma2(u64 a, u64 b, u64 c) {
    u64 d; asm("fma.rn.f32x2 %0, %1, %2, %3;" : "=l"(d) : "l"(a), "l"(b), "l"(c)); return d;
}
__device__ __forceinline__ u64 mul2(u64 a, u64 b) {
    u64 d; asm("mul.rn.f32x2 %0, %1, %2;" : "=l"(d) : "l"(a), "l"(b)); return d;
}

// Scratch (device globals; no allocation allowed)
__device__ float g_qf[BB*TT*FF*DC];   // [b][t][f][c]
__device__ float g_kf[BB*TT*FF*DC];   // [b][t][f][c]
__device__ float g_vv[BB*TT*FF*DC];   // [b][t][f][c]
__device__ float g_qt[BB*FF*TT*DC];   // [b][f][t][c]
__device__ float g_kt[BB*FF*TT*DC];   // [b][f][t][c]
__device__ float g_fo[BB*FF*TT*DC];   // [b][f][t][c]  (f_out, V of time-attn)

// ---------------------------------------------------------------------------
// Kernel 1: fused 1x1 convs (fqkv 64->48, tqk 64->32) + BN + PReLU, f32x2.
// ---------------------------------------------------------------------------
__global__ __launch_bounds__(256) void asa_conv(
    const float* __restrict__ inp,
    const float* __restrict__ fw, const float* __restrict__ fb,
    const float* __restrict__ fg, const float* __restrict__ fbe,
    const float* __restrict__ fm, const float* __restrict__ fv,
    const float* __restrict__ fa,
    const float* __restrict__ tw, const float* __restrict__ tb,
    const float* __restrict__ tg, const float* __restrict__ tbe,
    const float* __restrict__ tm, const float* __restrict__ tv,
    const float* __restrict__ ta)
{
    __shared__ __align__(16) float ws[64][80];   // [c][o], BN scale folded
    __shared__ float sh[80];
    __shared__ float al[2];
    int tid = threadIdx.x;

    for (int idx = tid; idx < 80*64; idx += 256) {
        int o = idx / 64, c = idx % 64;
        float w, g, vv;
        if (o < 48) { w = fw[o*64+c]; g = fg[o]; vv = fv[o]; }
        else        { int o2 = o-48; w = tw[o2*64+c]; g = tg[o2]; vv = tv[o2]; }
        ws[c][o] = w * (g * rsqrtf(vv + BN_EPS));
    }
    if (tid < 80) {
        int o = tid;
        float g, vv, m, b, be;
        if (o < 48) { g=fg[o]; vv=fv[o]; m=fm[o]; b=fb[o]; be=fbe[o]; }
        else        { int o2=o-48; g=tg[o2]; vv=tv[o2]; m=tm[o2]; b=tb[o2]; be=tbe[o2]; }
        sh[o] = (b - m) * (g * rsqrtf(vv + BN_EPS)) + be;
    }
    if (tid == 0) { al[0] = fa[0]; al[1] = ta[0]; }
    __syncthreads();

    int p = blockIdx.x * 256 + tid;
    if (p >= NPIX) return;
    int t = p % TT;
    int f = (p / TT) % FF;
    int b = p / (TT*FF);

    u64 acc2[40];
#pragma unroll
    for (int j = 0; j < 40; j++) acc2[j] = 0ull;

    const float* xp = inp + (b*CC*FF + f)*TT + t;
#pragma unroll 4
    for (int c = 0; c < 64; c++) {
        float x = __ldg(xp + c*FF*TT);
        u64 xx = pk2(x, x);
        const ulonglong2* wr = (const ulonglong2*)ws[c];
#pragma unroll
        for (int j = 0; j < 20; j++) {
            ulonglong2 w = wr[j];
            acc2[2*j+0] = fma2(xx, w.x, acc2[2*j+0]);
            acc2[2*j+1] = fma2(xx, w.y, acc2[2*j+1]);
        }
    }
    float acc[80];
#pragma unroll
    for (int j = 0; j < 40; j++) upk2(acc2[j], acc[2*j], acc[2*j+1]);

    float a0 = al[0], a1 = al[1];
    float yq[16], yk[16], yv[16];
#pragma unroll
    for (int c = 0; c < 16; c++) {
        float q = acc[3*c+0] + sh[3*c+0]; yq[c] = q >= 0.f ? q : a0*q;
        float k = acc[3*c+1] + sh[3*c+1]; yk[c] = k >= 0.f ? k : a0*k;
        float v = acc[3*c+2] + sh[3*c+2]; yv[c] = v >= 0.f ? v : a0*v;
    }
    int fbase = ((b*TT + t)*FF + f)*DC;
#pragma unroll
    for (int i = 0; i < 4; i++) {
        ((float4*)&g_qf[fbase])[i] = make_float4(yq[4*i],yq[4*i+1],yq[4*i+2],yq[4*i+3]);
        ((float4*)&g_kf[fbase])[i] = make_float4(yk[4*i],yk[4*i+1],yk[4*i+2],yk[4*i+3]);
        ((float4*)&g_vv[fbase])[i] = make_float4(yv[4*i],yv[4*i+1],yv[4*i+2],yv[4*i+3]);
    }
    float zq[16], zk[16];
#pragma unroll
    for (int c = 0; c < 16; c++) {
        float q = acc[48+2*c+0] + sh[48+2*c+0]; zq[c] = q >= 0.f ? q : a1*q;
        float k = acc[48+2*c+1] + sh[48+2*c+1]; zk[c] = k >= 0.f ? k : a1*k;
    }
    int tbase = ((b*FF + f)*TT + t)*DC;
#pragma unroll
    for (int i = 0; i < 4; i++) {
        ((float4*)&g_qt[tbase])[i] = make_float4(zq[4*i],zq[4*i+1],zq[4*i+2],zq[4*i+3]);
        ((float4*)&g_kt[tbase])[i] = make_float4(zk[4*i],zk[4*i+1],zk[4*i+2],zk[4*i+3]);
    }
}

// ---------------------------------------------------------------------------
// dot16 of packed query (8 u64) with one K/V row base (ulonglong2*).
// ---------------------------------------------------------------------------
__device__ __forceinline__ float dot16(const u64 q[8], const ulonglong2* kr)
{
    ulonglong2 ka = kr[0], kb = kr[1], kc = kr[2], kd = kr[3];
    u64 d0 = mul2(q[0], ka.x);
    u64 d1 = mul2(q[1], ka.y);
    d0 = fma2(q[2], kb.x, d0);
    d1 = fma2(q[3], kb.y, d1);
    d0 = fma2(q[4], kc.x, d0);
    d1 = fma2(q[5], kc.y, d1);
    d0 = fma2(q[6], kd.x, d0);
    d1 = fma2(q[7], kd.y, d1);
    float l0, h0, l1, h1;
    upk2(d0, l0, h0); upk2(d1, l1, h1);
    return (l0 + h0) + (l1 + h1);
}

__device__ __forceinline__ void pv16(u64 acc[8], u64 p2, const ulonglong2* vr)
{
    ulonglong2 v0 = vr[0], v1 = vr[1], v2 = vr[2], v3 = vr[3];
    acc[0] = fma2(p2, v0.x, acc[0]); acc[1] = fma2(p2, v0.y, acc[1]);
    acc[2] = fma2(p2, v1.x, acc[2]); acc[3] = fma2(p2, v1.y, acc[3]);
    acc[4] = fma2(p2, v2.x, acc[4]); acc[5] = fma2(p2, v2.y, acc[5]);
    acc[6] = fma2(p2, v3.x, acc[6]); acc[7] = fma2(p2, v3.y, acc[7]);
}

__device__ __forceinline__ void load_q16(const float* g, u64 q[8])
{
    const ulonglong2* qp = (const ulonglong2*)g;
    u64 s2 = pk2(SCALE, SCALE);
    ulonglong2 a = qp[0], b = qp[1], c = qp[2], d = qp[3];
    q[0]=mul2(a.x,s2); q[1]=mul2(a.y,s2); q[2]=mul2(b.x,s2); q[3]=mul2(b.y,s2);
    q[4]=mul2(c.x,s2); q[5]=mul2(c.y,s2); q[6]=mul2(d.x,s2); q[7]=mul2(d.y,s2);
}

// ---------------------------------------------------------------------------
// Kernel 2: frequency attention. One CTA per (b,t). 2 queries/thread,
// chunked (8) online softmax, f32x2.
// ---------------------------------------------------------------------------
__global__ __launch_bounds__(160) void asa_fattn()
{
    __shared__ __align__(16) float Ks[FF*DC];
    __shared__ __align__(16) float Vs[FF*DC];
    int bt = blockIdx.x;
    int b = bt / TT, t = bt % TT;
    int base = (b*TT + t)*FF*DC;
    int tid = threadIdx.x;
    for (int i = tid; i < FF*DC/4; i += 160) {
        ((float4*)Ks)[i] = ((const float4*)(g_kf + base))[i];
        ((float4*)Vs)[i] = ((const float4*)(g_vv + base))[i];
    }
    __syncthreads();
    if (tid > 128) return;

    int fA = (tid < 128) ? tid : 256;
    int fB = (tid < 128) ? tid + 128 : 256;
    bool hasB = (tid < 128);

    u64 qA[8], qB[8];
    load_q16(g_qf + base + fA*DC, qA);
    load_q16(g_qf + base + fB*DC, qB);

    float mA = -3.0e38f, lA = 0.f, mB = -3.0e38f, lB = 0.f;
    u64 accA[8], accB[8];
#pragma unroll
    for (int j = 0; j < 8; j++) { accA[j] = 0ull; accB[j] = 0ull; }

    for (int y0 = 0; y0 < 256; y0 += 8) {
        float sA[8], sB[8];
#pragma unroll
        for (int i = 0; i < 8; i++) {
            const ulonglong2* kr = (const ulonglong2*)(Ks + (y0+i)*DC);
            sA[i] = dot16(qA, kr);
            sB[i] = dot16(qB, kr);
        }
        float cmA = fmaxf(fmaxf(fmaxf(sA[0],sA[1]),fmaxf(sA[2],sA[3])),
                          fmaxf(fmaxf(sA[4],sA[5]),fmaxf(sA[6],sA[7])));
        float cmB = fmaxf(fmaxf(fmaxf(sB[0],sB[1]),fmaxf(sB[2],sB[3])),
                          fmaxf(fmaxf(sB[4],sB[5]),fmaxf(sB[6],sB[7])));
        float mnA = fmaxf(mA, cmA), mnB = fmaxf(mB, cmB);
        float corrA = __expf(mA - mnA), corrB = __expf(mB - mnB);
        mA = mnA; mB = mnB;
        u64 cA2 = pk2(corrA, corrA), cB2 = pk2(corrB, corrB);
#pragma unroll
        for (int j = 0; j < 8; j++) { accA[j] = mul2(accA[j], cA2); accB[j] = mul2(accB[j], cB2); }
        float psA = 0.f, psB = 0.f;
#pragma unroll
        for (int i = 0; i < 8; i++) {
            const ulonglong2* vr = (const ulonglong2*)(Vs + (y0+i)*DC);
            float pa = __expf(sA[i] - mnA); psA += pa;
            float pb = __expf(sB[i] - mnB); psB += pb;
            pv16(accA, pk2(pa, pa), vr);
            pv16(accB, pk2(pb, pb), vr);
        }
        lA = fmaf(lA, corrA, psA);
        lB = fmaf(lB, corrB, psB);
    }
    // tail y = 256
    {
        const ulonglong2* kr = (const ulonglong2*)(Ks + 256*DC);
        const ulonglong2* vr = (const ulonglong2*)(Vs + 256*DC);
        float sA = dot16(qA, kr), sB = dot16(qB, kr);
        float mnA = fmaxf(mA, sA), mnB = fmaxf(mB, sB);
        float corrA = __expf(mA - mnA), corrB = __expf(mB - mnB);
        float pa = __expf(sA - mnA), pb = __expf(sB - mnB);
        u64 cA2 = pk2(corrA, corrA), cB2 = pk2(corrB, corrB);
#pragma unroll
        for (int j = 0; j < 8; j++) { accA[j] = mul2(accA[j], cA2); accB[j] = mul2(accB[j], cB2); }
        pv16(accA, pk2(pa, pa), vr);
        pv16(accB, pk2(pb, pb), vr);
        lA = fmaf(lA, corrA, pa);
        lB = fmaf(lB, corrB, pb);
    }
    // store
    {
        float inv = 1.f / lA;
        u64 iv = pk2(inv, inv);
        float* op = g_fo + ((b*FF + fA)*TT + t)*DC;
#pragma unroll
        for (int j = 0; j < 4; j++) {
            float x0,x1,x2,x3;
            upk2(mul2(accA[2*j],iv), x0, x1);
            upk2(mul2(accA[2*j+1],iv), x2, x3);
            ((float4*)op)[j] = make_float4(x0,x1,x2,x3);
        }
    }
    if (hasB) {
        float inv = 1.f / lB;
        u64 iv = pk2(inv, inv);
        float* op = g_fo + ((b*FF + fB)*TT + t)*DC;
#pragma unroll
        for (int j = 0; j < 4; j++) {
            float x0,x1,x2,x3;
            upk2(mul2(accB[2*j],iv), x0, x1);
            upk2(mul2(accB[2*j+1],iv), x2, x3);
            ((float4*)op)[j] = make_float4(x0,x1,x2,x3);
        }
    }
}

// ---------------------------------------------------------------------------
// Kernel 3: causal time attention + proj + residual. 2 CTAs per (b,f);
// thread handles query pair (p, 499-p), chunked f32x2 softmax.
// ---------------------------------------------------------------------------
__device__ __forceinline__ void proj_store2(
    const float* __restrict__ pws, const float* __restrict__ psh, float alpha,
    const float* __restrict__ inp, float* __restrict__ out,
    int b, int f, int t, const u64 acc[8], float l)
{
    u64 o2[8];
    float inv = 1.f / l;
    u64 iv = pk2(inv, inv);
#pragma unroll
    for (int j = 0; j < 8; j++) o2[j] = mul2(acc[j], iv);
    int base = b*CC*FF*TT + f*TT + t;
#pragma unroll 4
    for (int co = 0; co < 64; co++) {
        const ulonglong2* wr = (const ulonglong2*)(pws + co*16);
        ulonglong2 wa = wr[0], wb = wr[1], wc = wr[2], wd = wr[3];
        u64 d0 = mul2(wa.x, o2[0]);
        u64 d1 = mul2(wa.y, o2[1]);
        d0 = fma2(wb.x, o2[2], d0);
        d1 = fma2(wb.y, o2[3], d1);
        d0 = fma2(wc.x, o2[4], d0);
        d1 = fma2(wc.y, o2[5], d1);
        d0 = fma2(wd.x, o2[6], d0);
        d1 = fma2(wd.y, o2[7], d1);
        float l0,h0,l1,h1;
        upk2(d0,l0,h0); upk2(d1,l1,h1);
        float r = psh[co] + (l0+h0) + (l1+h1);
        r = r >= 0.f ? r : alpha * r;
        int idx = base + co*FF*TT;
        out[idx] = r + __ldg(&inp[idx]);
    }
}

extern __shared__ float sm3[];
__global__ __launch_bounds__(128) void asa_tattn(
    const float* __restrict__ inp,
    const float* __restrict__ pw, const float* __restrict__ pb,
    const float* __restrict__ pg, const float* __restrict__ pbe,
    const float* __restrict__ pm, const float* __restrict__ pv,
    const float* __restrict__ pa,
    float* __restrict__ out)
{
    float* Ks  = sm3;                 // TTP*DC
    float* Vs  = sm3 + TTP*DC;        // TTP*DC
    float* pws = Vs + TTP*DC;         // 64*16
    float* psh = pws + 64*16;         // 64
    __shared__ float s_alpha;

    int bf   = blockIdx.x >> 1;
    int half = blockIdx.x & 1;
    int b = bf / FF, f = bf % FF;
    int base = bf * TT * DC;
    int tid = threadIdx.x;

    for (int i = tid; i < TTP*DC/4; i += 128) {
        float4 kk = make_float4(0,0,0,0), vv = kk;
        if (i < TT*DC/4) {
            kk = ((const float4*)(g_kt + base))[i];
            vv = ((const float4*)(g_fo + base))[i];
        }
        ((float4*)Ks)[i] = kk;
        ((float4*)Vs)[i] = vv;
    }
    for (int i = tid; i < 64*16; i += 128) {
        int o = i >> 4;
        pws[i] = pw[i] * (pg[o] * rsqrtf(pv[o] + BN_EPS));
    }
    if (tid < 64) {
        int o = tid;
        psh[o] = (pb[o] - pm[o]) * (pg[o] * rsqrtf(pv[o] + BN_EPS)) + pbe[o];
    }
    if (tid == 0) s_alpha = pa[0];
    __syncthreads();

    if (tid >= 125) return;
    float alpha = s_alpha;
    int p  = tid + half*125;     // 0..249
    int t1 = p;
    int t2 = TT - 1 - p;         // t2 > t1

    u64 q1[8], q2[8];
    load_q16(g_qt + base + t1*DC, q1);
    load_q16(g_qt + base + t2*DC, q2);

    float m1 = -3.0e38f, l1 = 0.f, m2 = -3.0e38f, l2 = 0.f;
    u64 a1[8], a2[8];
#pragma unroll
    for (int j = 0; j < 8; j++) { a1[j] = 0ull; a2[j] = 0ull; }

    for (int y0 = 0; y0 <= t2; y0 += 8) {
        bool doq1 = (y0 <= t1);
        float s1[8], s2[8];
#pragma unroll
        for (int i = 0; i < 8; i++) {
            int y = y0 + i;
            const ulonglong2* kr = (const ulonglong2*)(Ks + y*DC);
            float v2 = dot16(q2, kr);
            s2[i] = (y <= t2) ? v2 : -3.0e38f;
            if (doq1) {
                float v1 = dot16(q1, kr);
                s1[i] = (y <= t1) ? v1 : -3.0e38f;
            }
        }
        // q2 update (always)
        {
            float cm = fmaxf(fmaxf(fmaxf(s2[0],s2[1]),fmaxf(s2[2],s2[3])),
                             fmaxf(fmaxf(s2[4],s2[5]),fmaxf(s2[6],s2[7])));
            float mn = fmaxf(m2, cm);
            float corr = __expf(m2 - mn);
            m2 = mn;
            u64 c2 = pk2(corr, corr);
#pragma unroll
            for (int j = 0; j < 8; j++) a2[j] = mul2(a2[j], c2);
            float ps = 0.f;
#pragma unroll
            for (int i = 0; i < 8; i++) {
                const ulonglong2* vr = (const ulonglong2*)(Vs + (y0+i)*DC);
                float pr = __expf(s2[i] - mn); ps += pr;
                pv16(a2, pk2(pr, pr), vr);
            }
            l2 = fmaf(l2, corr, ps);
        }
        if (doq1) {
            float cm = fmaxf(fmaxf(fmaxf(s1[0],s1[1]),fmaxf(s1[2],s1[3])),
                             fmaxf(fmaxf(s1[4],s1[5]),fmaxf(s1[6],s1[7])));
            float mn = fmaxf(m1, cm);
            float corr = __expf(m1 - mn);
            m1 = mn;
            u64 c2 = pk2(corr, corr);
#pragma unroll
            for (int j = 0; j < 8; j++) a1[j] = mul2(a1[j], c2);
            float ps = 0.f;
#pragma unroll
            for (int i = 0; i < 8; i++) {
                const ulonglong2* vr = (const ulonglong2*)(Vs + (y0+i)*DC);
                float pr = __expf(s1[i] - mn); ps += pr;
                pv16(a1, pk2(pr, pr), vr);
            }
            l1 = fmaf(l1, corr, ps);
        }
    }
    proj_store2(pws, psh, alpha, inp, out, b, f, t1, a1, l1);
    proj_store2(pws, psh, alpha, inp, out, b, f, t2, a2, l2);
}

// ---------------------------------------------------------------------------
extern "C" void kernel_launch(void* const* d_in, const int* in_sizes, int n_in,
                              void* d_out, int out_size)
{
    const float* inp = (const float*)d_in[0];
    asa_conv<<<(NPIX + 255)/256, 256>>>(
        inp,
        (const float*)d_in[1],  (const float*)d_in[2],  (const float*)d_in[3],
        (const float*)d_in[4],  (const float*)d_in[5],  (const float*)d_in[6],
        (const float*)d_in[7],
        (const float*)d_in[8],  (const float*)d_in[9],  (const float*)d_in[10],
        (const float*)d_in[11], (const float*)d_in[12], (const float*)d_in[13],
        (const float*)d_in[14]);

    asa_fattn<<<BB*TT, 160>>>();

    int smem = (TTP*DC*2 + 64*16 + 64) * (int)sizeof(float);
    cudaFuncSetAttribute(asa_tattn, cudaFuncAttributeMaxDynamicSharedMemorySize, smem);
    asa_tattn<<<BB*FF*2, 128, smem>>>(
        inp,
        (const float*)d_in[15], (const float*)d_in[16], (const float*)d_in[17],
        (const float*)d_in[18], (const float*)d_in[19], (const float*)d_in[20],
        (const float*)d_in[21],
        (float*)d_out);
}